// round 5
// baseline (speedup 1.0000x reference)
#include <cuda_runtime.h>

#define BB 4
#define LL 5
#define CC 256
#define HH 100
#define WW 252
#define HWTOT (HH*WW)        // 25200
#define BL (BB*LL)           // 20
#define CP 2
#define KSEL 1024
#define HW4 (HWTOT/4)        // 6300
#define CHW4 (CC*HWTOT/4)    // 1,612,800 float4 per (b,l)

// Scratch (device globals — no allocation allowed in kernel_launch)
__device__ float         g_fmap[BL*HWTOT];     // ~2 MB
__device__ unsigned      g_thresh[BL];
__device__ unsigned char g_factor[BL*HWTOT];   // ~0.5 MB

// ---------------------------------------------------------------------------
// 1) fmap[b,l,hw] = sigmoid(max_cp(psm[b,l,cp,hw] - psm[b,0,cp,hw]))
// sigmoid is monotone, so max commutes through it.
// ---------------------------------------------------------------------------
__global__ void fmap_kernel(const float* __restrict__ psm) {
    int idx = blockIdx.x * blockDim.x + threadIdx.x;
    if (idx >= BL * HWTOT) return;
    int bl = idx / HWTOT;
    int hw = idx - bl * HWTOT;
    int b  = bl / LL;
    const float* p = psm + (size_t)bl * CP * HWTOT + hw;        // psm[b,l,0,hw]
    const float* e = psm + (size_t)b * LL * CP * HWTOT + hw;    // psm[b,0,0,hw]
    float d0 = p[0]     - e[0];
    float d1 = p[HWTOT] - e[HWTOT];
    float d  = fmaxf(d0, d1);
    g_fmap[idx] = 1.0f / (1.0f + expf(-d));
}

// ---------------------------------------------------------------------------
// 2) Per-(b,l) radix select of K-th largest fmap value.
// fmap in (0,1) -> positive floats -> uint bit pattern is order-isomorphic.
// 4 rounds of 8-bit MSB-first histogram select. Exact K-th value, so the
// ">= thresh" mask has identical tie semantics to the reference.
// ---------------------------------------------------------------------------
__global__ void select_kernel() {
    int bl = blockIdx.x;
    const float* v = g_fmap + (size_t)bl * HWTOT;
    __shared__ unsigned hist[256];
    __shared__ unsigned s_prefix, s_k;
    if (threadIdx.x == 0) { s_prefix = 0u; s_k = KSEL; }
    for (int shift = 24; shift >= 0; shift -= 8) {
        for (int i = threadIdx.x; i < 256; i += blockDim.x) hist[i] = 0;
        __syncthreads();
        unsigned pre     = s_prefix;
        unsigned premask = (shift == 24) ? 0u : (0xFFFFFFFFu << (shift + 8));
        for (int i = threadIdx.x; i < HWTOT; i += blockDim.x) {
            unsigned u = __float_as_uint(v[i]);
            if ((u & premask) == pre)
                atomicAdd(&hist[(u >> shift) & 0xFFu], 1u);
        }
        __syncthreads();
        if (threadIdx.x == 0) {
            unsigned k = s_k, cum = 0;
            int bin = 255;
            for (; bin > 0; bin--) {
                if (cum + hist[bin] >= k) break;
                cum += hist[bin];
            }
            s_prefix = pre | ((unsigned)bin << shift);
            s_k      = k - cum;
        }
        __syncthreads();
    }
    if (threadIdx.x == 0) g_thresh[bl] = s_prefix;
}

// ---------------------------------------------------------------------------
// 3) Fold l==0, mask, and fmap>=thresh into a single 0/1 byte per (b,l,hw).
// ---------------------------------------------------------------------------
__global__ void factor_kernel(const int* __restrict__ mask) {
    int idx = blockIdx.x * blockDim.x + threadIdx.x;
    if (idx >= BL * HWTOT) return;
    int bl = idx / HWTOT;
    int l  = bl % LL;
    unsigned char f;
    if (l == 0)                 f = 1;
    else if (mask[bl] == 0)     f = 0;
    else f = (__float_as_uint(g_fmap[idx]) >= g_thresh[bl]) ? 1 : 0;
    g_factor[idx] = f;
}

// ---------------------------------------------------------------------------
// 4) Heavy streaming pass: out = x * factor, factor broadcast over C=256.
// Load factor FIRST; if the whole float4's factor is zero, skip reading x
// (saves ~96% of reads on kept l>0 slices and 100% on masked-out slices).
// Output is write-once -> __stcs streaming store keeps L2 for factor/x.
// ---------------------------------------------------------------------------
__global__ void apply_kernel(const float4* __restrict__ x,
                             float4* __restrict__ out) {
    int bl  = blockIdx.y;
    int idx = blockIdx.x * blockDim.x + threadIdx.x;   // [0, CHW4), exact
    size_t g = (size_t)bl * CHW4 + idx;
    int hw4 = idx % HW4;
    uchar4 f = __ldg(reinterpret_cast<const uchar4*>(g_factor + bl * HWTOT + hw4 * 4));
    float4 v;
    if ((f.x | f.y | f.z | f.w) == 0) {
        v = make_float4(0.f, 0.f, 0.f, 0.f);
    } else {
        v = __ldg(x + g);
        v.x *= (float)f.x; v.y *= (float)f.y;
        v.z *= (float)f.z; v.w *= (float)f.w;
    }
    __stcs(out + g, v);
}

// ---------------------------------------------------------------------------
extern "C" void kernel_launch(void* const* d_in, const int* in_sizes, int n_in,
                              void* d_out, int out_size) {
    const float* x    = (const float*)d_in[0];
    const float* psm  = (const float*)d_in[1];
    const int*   mask = (const int*)d_in[2];

    fmap_kernel<<<(BL * HWTOT + 255) / 256, 256>>>(psm);
    select_kernel<<<BL, 1024>>>();
    factor_kernel<<<(BL * HWTOT + 255) / 256, 256>>>(mask);

    dim3 grid(CHW4 / 256, BL);   // 6300 x 20 blocks, 1 float4/thread
    apply_kernel<<<grid, 256>>>((const float4*)x, (float4*)d_out);
}

// round 7
// speedup vs baseline: 1.0816x; 1.0816x over previous
#include <cuda_runtime.h>

#define BB 4
#define LL 5
#define CC 256
#define HH 100
#define WW 252
#define HWTOT (HH*WW)        // 25200
#define BL (BB*LL)           // 20
#define CP 2
#define KSEL 1024
#define HW4 (HWTOT/4)        // 6300
#define CHW4 (CC*HWTOT/4)    // 1,612,800 float4 per (b,l)
#define NPT 25               // values per thread in prep (1024*25 >= 25200)

__device__ unsigned char g_factor[BL*HWTOT];   // ~0.5 MB

// ---------------------------------------------------------------------------
// Fused prep: one block per (b,l).
//  l==0            -> factor = 1 everywhere (no fmap/select needed)
//  mask==0, l>0    -> factor = 0 everywhere
//  else            -> compute fmap = sigmoid(max_cp(psm - ego)) into REGISTERS,
//                     radix-select exact K-th largest (float bits of positive
//                     sigmoid are order-isomorphic), write factor = (v >= thr).
// Tie semantics (>=) identical to reference.
// ---------------------------------------------------------------------------
__global__ __launch_bounds__(1024) void prep_kernel(const float* __restrict__ psm,
                                                    const int* __restrict__ mask) {
    int bl = blockIdx.x;
    int l  = bl % LL;
    int b  = bl / LL;
    unsigned char* fac = g_factor + bl * HWTOT;
    int tid = threadIdx.x;

    if (l == 0) {
        for (int i = tid; i < HWTOT; i += 1024) fac[i] = 1;
        return;
    }
    if (mask[bl] == 0) {
        for (int i = tid; i < HWTOT; i += 1024) fac[i] = 0;
        return;
    }

    const float* p = psm + (size_t)bl * CP * HWTOT;          // psm[b,l,0,:]
    const float* e = psm + (size_t)b * LL * CP * HWTOT;      // psm[b,0,0,:]

    // fmap values in registers (fixed unrolled array; last slot conditional)
    unsigned vals[NPT];
    #pragma unroll
    for (int k = 0; k < NPT; k++) {
        int i = tid + k * 1024;
        unsigned u = 0;
        if (k < 24 || i < HWTOT) {
            float d0 = __ldg(p + i)         - __ldg(e + i);
            float d1 = __ldg(p + i + HWTOT) - __ldg(e + i + HWTOT);
            float d  = fmaxf(d0, d1);
            u = __float_as_uint(1.0f / (1.0f + expf(-d)));
        }
        vals[k] = u;
    }

    // MSB-first 8-bit radix select of K-th largest (values positive: bit order = value order)
    __shared__ unsigned hist[256];
    __shared__ unsigned s_prefix, s_k;
    if (tid == 0) { s_prefix = 0u; s_k = KSEL; }

    for (int shift = 24; shift >= 0; shift -= 8) {
        for (int i = tid; i < 256; i += 1024) hist[i] = 0;
        __syncthreads();
        unsigned pre     = s_prefix;
        unsigned premask = (shift == 24) ? 0u : (0xFFFFFFFFu << (shift + 8));
        #pragma unroll
        for (int k = 0; k < NPT; k++) {
            int i = tid + k * 1024;
            if ((k < 24 || i < HWTOT) && (vals[k] & premask) == pre)
                atomicAdd(&hist[(vals[k] >> shift) & 0xFFu], 1u);
        }
        __syncthreads();
        if (tid == 0) {
            unsigned k = s_k, cum = 0;
            int bin = 255;
            for (; bin > 0; bin--) {
                if (cum + hist[bin] >= k) break;
                cum += hist[bin];
            }
            s_prefix = pre | ((unsigned)bin << shift);
            s_k      = k - cum;
        }
        __syncthreads();
    }

    unsigned thr = s_prefix;
    #pragma unroll
    for (int k = 0; k < NPT; k++) {
        int i = tid + k * 1024;
        if (k < 24 || i < HWTOT)
            fac[i] = (vals[k] >= thr) ? 1 : 0;
    }
}

// ---------------------------------------------------------------------------
// Heavy streaming pass: out = x * factor (factor broadcast over C=256).
// 4 float4 per thread: batch factor loads (MLP=4 on the L2-latency chain),
// then predicated x loads (skip read when the whole float4 is gated), then
// streaming stores. Stores (516 MB) are the BW floor.
// ---------------------------------------------------------------------------
__global__ __launch_bounds__(256) void apply_kernel(const float4* __restrict__ x,
                                                    float4* __restrict__ out) {
    int bl   = blockIdx.y;
    int base = blockIdx.x * 1024 + threadIdx.x;   // block covers 1024 float4s
    const unsigned char* fac = g_factor + bl * HWTOT;

    int      idx[4];
    uchar4   f[4];
    #pragma unroll
    for (int j = 0; j < 4; j++) {
        idx[j] = base + j * 256;                  // < CHW4 exactly (1575*1024)
        int hw4 = idx[j] % HW4;
        f[j] = __ldg(reinterpret_cast<const uchar4*>(fac + hw4 * 4));
    }

    float4 v[4];
    #pragma unroll
    for (int j = 0; j < 4; j++) {
        if ((f[j].x | f[j].y | f[j].z | f[j].w) == 0) {
            v[j] = make_float4(0.f, 0.f, 0.f, 0.f);
        } else {
            v[j] = __ldg(x + (size_t)bl * CHW4 + idx[j]);
            v[j].x *= (float)f[j].x; v[j].y *= (float)f[j].y;
            v[j].z *= (float)f[j].z; v[j].w *= (float)f[j].w;
        }
    }

    #pragma unroll
    for (int j = 0; j < 4; j++)
        __stcs(out + (size_t)bl * CHW4 + idx[j], v[j]);
}

// ---------------------------------------------------------------------------
extern "C" void kernel_launch(void* const* d_in, const int* in_sizes, int n_in,
                              void* d_out, int out_size) {
    const float* x    = (const float*)d_in[0];
    const float* psm  = (const float*)d_in[1];
    const int*   mask = (const int*)d_in[2];

    prep_kernel<<<BL, 1024>>>(psm, mask);

    dim3 grid(CHW4 / 1024, BL);    // 1575 x 20 blocks, 4 float4/thread
    apply_kernel<<<grid, 256>>>((const float4*)x, (float4*)d_out);
}